// round 8
// baseline (speedup 1.0000x reference)
#include <cuda_runtime.h>

// ---------------- problem constants ----------------
constexpr int NAg = 10240;           // B*NA agents
constexpr int NE  = 10, NAL = 9;
constexpr int PEc = NAg * NE;        // 102400 enemy pairs
constexpr int PAc = NAg * NAL;       // 92160 ally pairs
constexpr int REc = 2 * PEc;         // 204800 enemy rows (pair,comp)
constexpr int RAc = 2 * PAc;         // 184320 ally rows
constexpr int RTc = REc + RAc;       // 389120
constexpr float EPS_ = 1e-5f;

// sumsq slots (within double ss block)
constexpr int SS_E1 = 0,   SS_A1 = 64,  SS_E2 = 128, SS_A2 = 192;
constexpr int SS_F1 = 256, SS_F2 = 320;
constexpr int SS_IE1 = 384, SS_IA1 = 448, SS_IE2 = 512, SS_IA2 = 576;
constexpr int SS_IE3 = 640, SS_IA3 = 641;

// ---------------- scratch layout (floats) ----------------
constexpr size_t OFF_Y1   = 0;
constexpr size_t OFF_Y2   = OFF_Y1   + (size_t)RTc * 64;
constexpr size_t OFF_ESC  = OFF_Y2   + (size_t)RTc * 64;
constexpr size_t OFF_POOL = OFF_ESC  + (size_t)PEc * 64;
constexpr size_t OFF_YF1  = OFF_POOL + (size_t)NAg * 128;
constexpr size_t OFF_VF   = OFF_YF1  + (size_t)NAg * 128;
constexpr size_t OFF_SF   = OFF_VF   + (size_t)NAg * 128;
constexpr size_t OFF_VCE  = OFF_SF   + (size_t)NAg * 64;
constexpr size_t OFF_VCA  = OFF_VCE  + (size_t)NAg * 128;
constexpr size_t OFF_SFC  = OFF_VCA  + (size_t)NAg * 128;
constexpr size_t OFF_YI1E = OFF_SFC  + (size_t)NAg * 128;
constexpr size_t OFF_YI1A = OFF_YI1E + (size_t)REc * 64;
constexpr size_t OFF_YI2E = OFF_YI1A + (size_t)REc * 64;
constexpr size_t OFF_YI2A = OFF_YI2E + (size_t)REc * 64;
constexpr size_t OFF_Y3   = OFF_YI2A + (size_t)REc * 64;
constexpr size_t OFF_H1   = OFF_Y3   + (size_t)2 * REc;
constexpr size_t OFF_H2   = OFF_H1   + (size_t)PEc * 128;
constexpr size_t OFF_OAH  = OFF_H2   + (size_t)PEc * 64;
constexpr size_t OFF_MV   = OFF_OAH  + (size_t)NAg * 64;
constexpr size_t SCR_TOTAL = OFF_MV + 20480;

__device__ __align__(16) float g_scratch[SCR_TOTAL];
__device__ __align__(16) double g_ssd[768];

// ---------------- zero kernel (mv floats + ss doubles) ----------------
__global__ void zero_k(float* __restrict__ mv, double* __restrict__ ssd) {
    int i = blockIdx.x * 256 + threadIdx.x;
    if (i < 20480) mv[i] = 0.f;
    if (i < 768) ssd[i] = 0.0;
}

// ---------------- layer1: build_vec (ref-exact fp32) + 19-dot + sumsq ------
__global__ void __launch_bounds__(64) layer1_k(
    const float* __restrict__ own,     // (NAg, 11)
    const float* __restrict__ efeat,   // (PEc, 9)
    const float* __restrict__ afeat,   // (PAc, 9)
    const float* __restrict__ We,      // (19, 64)
    const float* __restrict__ Wa,      // (19, 64)
    float* __restrict__ y1,            // (RTc, 64)
    double* __restrict__ ssd)
{
    constexpr int PPB = 32;
    constexpr int EBLK = PEc / PPB;  // 3200
    const bool isE = blockIdx.x < EBLK;
    const int pbase = (isE ? blockIdx.x : blockIdx.x - EBLK) * PPB;
    const float* W = isE ? We : Wa;
    const float* feats = isE ? efeat : afeat;
    const int nper = isE ? NE : NAL;
    const int tid = threadIdx.x;

    __shared__ float ev0[PPB][20];   // comp-0 rows of ev (19 cols)
    __shared__ float ev1[PPB][20];   // comp-1 rows

    if (tid < PPB) {
        int p = pbase + tid;
        const float* f = feats + (size_t)p * 9;
        const float* o = own + (size_t)(p / nper) * 11;
        float f2 = f[2], f3 = f[3];
        // pos_mod = sqrt(f2*f2 + f3*f3), exact ref op order
        float pm = __fsqrt_rn(__fadd_rn(__fmul_rn(f2, f2), __fmul_rn(f3, f3)));
        bool mask = (pm == 0.f);
        float denom = mask ? 1.f : pm;
        // column 0: pos itself
        ev0[tid][0] = f2; ev1[tid][0] = f3;
        // columns 1..7: other_mod = sqrt((2*f)*f); coff = other_mod/denom (0 if mask)
        float oth[7] = { f[0], f[1], f[4], f[5], f[6], f[7], f[8] };
        #pragma unroll
        for (int k = 0; k < 7; k++) {
            float om = __fsqrt_rn(__fmul_rn(2.f * oth[k], oth[k]));
            float u = mask ? 0.f : __fdiv_rn(om, denom);
            ev0[tid][1 + k] = __fmul_rn(f2, u);
            ev1[tid][1 + k] = __fmul_rn(f3, u);
        }
        // columns 8..18: own_mod = sqrt(fl(o^2)+fl(o^2))
        #pragma unroll
        for (int k = 0; k < 11; k++) {
            float q = __fmul_rn(o[k], o[k]);
            float om = __fsqrt_rn(__fadd_rn(q, q));
            float u = mask ? 0.f : __fdiv_rn(om, denom);
            ev0[tid][8 + k] = __fmul_rn(f2, u);
            ev1[tid][8 + k] = __fmul_rn(f3, u);
        }
    }
    __syncthreads();

    float wr[19];
    #pragma unroll
    for (int k = 0; k < 19; k++) wr[k] = __ldg(W + k * 64 + tid);

    float ssa = 0.f;
    size_t rowG0 = (isE ? (size_t)0 : (size_t)REc) + (size_t)pbase * 2;
    for (int j = 0; j < PPB; j++) {
        float s0 = 0.f, s1 = 0.f;
        #pragma unroll
        for (int k = 0; k < 19; k++) {          // ascending k, single accumulator
            s0 = fmaf(ev0[j][k], wr[k], s0);
            s1 = fmaf(ev1[j][k], wr[k], s1);
        }
        y1[(rowG0 + 2 * j) * 64 + tid]     = s0;
        y1[(rowG0 + 2 * j + 1) * 64 + tid] = s1;
        ssa += s0 * s0 + s1 * s1;
    }
    atomicAdd(ssd + (isE ? SS_E1 : SS_A1) + tid, (double)ssa);
}

// ---------------- qbn + qrelu in place (ref-exact fp32 ops), opt qmerge ----
__global__ void act_k(float* __restrict__ y, const double* __restrict__ ssd,
                      int npairs, double invN, float* __restrict__ mergeOut)
{
    int idx = blockIdx.x * blockDim.x + threadIdx.x;
    if (idx >= npairs * 64) return;
    int p = idx >> 6, c = idx & 63;
    float m = (float)(ssd[c] * invN);                       // correctly-rounded mean
    float denom = __fsqrt_rn(__fadd_rn(m, EPS_));
    size_t i0 = (size_t)p * 128 + c;
    float a = __fdiv_rn(y[i0], denom);
    float b = __fdiv_rn(y[i0 + 64], denom);
    float mod = __fsqrt_rn(__fadd_rn(__fmul_rn(a, a), __fmul_rn(b, b)));
    float coeff = __fdiv_rn(mod, fmaxf(1.f, mod));
    a = __fmul_rn(a, coeff); b = __fmul_rn(b, coeff);
    y[i0] = a; y[i0 + 64] = b;
    if (mergeOut)
        mergeOut[(size_t)p * 64 + c] = __fadd_rn(__fmul_rn(a, a), __fmul_rn(b, b));
}

// ---------------- generic GEMM: out = in @ W (+add) (relu) (+sumsq) ----------
// ADDMODE: 0 none; 1 bias (N); 2 row-mapped ar=((r>>1)/NE)*2+(r&1); 3 ar=r/NE
template<int K, int N, int ADDMODE, bool RELU, bool WITH_SS>
__global__ void __launch_bounds__(256) gemm_k(
    const float* __restrict__ in, float* __restrict__ out,
    const float* __restrict__ W, const float* __restrict__ addp,
    double* __restrict__ ssOut)
{
    constexpr int CG = N / 4;
    constexpr int RG = 256 / CG;
    constexpr int TILE_R = RG * 4;
    __shared__ float xs[TILE_R][K + 4];
    __shared__ float ssh[WITH_SS ? RG * N : 1];

    const int tid = threadIdx.x;
    const int cg = tid % CG;
    const int rg = tid / CG;
    const int rowBase = blockIdx.x * TILE_R;

    {
        constexpr int KV = K / 4;
        for (int i = tid; i < TILE_R * KV; i += 256) {
            int r = i / KV, c = i - r * KV;
            float4 v = __ldg(reinterpret_cast<const float4*>(in + (size_t)(rowBase + r) * K) + c);
            *reinterpret_cast<float4*>(&xs[r][c * 4]) = v;
        }
    }
    __syncthreads();

    float acc[4][4];
    #pragma unroll
    for (int i = 0; i < 4; i++)
        #pragma unroll
        for (int j = 0; j < 4; j++) acc[i][j] = 0.f;

    const float4* Wv = reinterpret_cast<const float4*>(W);
    const int r4 = rg * 4;
    #pragma unroll 2
    for (int k0 = 0; k0 < K; k0 += 4) {
        float xa[4][4];
        #pragma unroll
        for (int i = 0; i < 4; i++)
            *reinterpret_cast<float4*>(xa[i]) = *reinterpret_cast<const float4*>(&xs[r4 + i][k0]);
        #pragma unroll
        for (int kk = 0; kk < 4; kk++) {        // ascending k, single accumulator/output
            float4 b = __ldg(Wv + (k0 + kk) * CG + cg);
            #pragma unroll
            for (int i = 0; i < 4; i++) {
                float a = xa[i][kk];
                acc[i][0] = fmaf(a, b.x, acc[i][0]);
                acc[i][1] = fmaf(a, b.y, acc[i][1]);
                acc[i][2] = fmaf(a, b.z, acc[i][2]);
                acc[i][3] = fmaf(a, b.w, acc[i][3]);
            }
        }
    }

    float ssl[4] = {0.f, 0.f, 0.f, 0.f};
    #pragma unroll
    for (int i = 0; i < 4; i++) {
        int r = rowBase + r4 + i;
        float4 a = make_float4(acc[i][0], acc[i][1], acc[i][2], acc[i][3]);
        if (ADDMODE == 1) {
            float4 bb = __ldg(reinterpret_cast<const float4*>(addp) + cg);
            a.x += bb.x; a.y += bb.y; a.z += bb.z; a.w += bb.w;
        } else if (ADDMODE == 2) {
            int ar = ((r >> 1) / NE) * 2 + (r & 1);
            float4 bb = __ldg(reinterpret_cast<const float4*>(addp + (size_t)ar * N) + cg);
            a.x += bb.x; a.y += bb.y; a.z += bb.z; a.w += bb.w;
        } else if (ADDMODE == 3) {
            int ar = r / NE;
            float4 bb = __ldg(reinterpret_cast<const float4*>(addp + (size_t)ar * N) + cg);
            a.x += bb.x; a.y += bb.y; a.z += bb.z; a.w += bb.w;
        }
        if (WITH_SS) {
            ssl[0] += a.x * a.x; ssl[1] += a.y * a.y;
            ssl[2] += a.z * a.z; ssl[3] += a.w * a.w;
        }
        if (RELU) {
            a.x = fmaxf(a.x, 0.f); a.y = fmaxf(a.y, 0.f);
            a.z = fmaxf(a.z, 0.f); a.w = fmaxf(a.w, 0.f);
        }
        *(reinterpret_cast<float4*>(out + (size_t)r * N) + cg) = a;
    }

    if (WITH_SS) {
        *reinterpret_cast<float4*>(&ssh[rg * N + cg * 4]) =
            make_float4(ssl[0], ssl[1], ssl[2], ssl[3]);
        __syncthreads();
        if (tid < N) {
            float s = 0.f;
            #pragma unroll
            for (int g = 0; g < RG; g++) s += ssh[g * N + tid];
            atomicAdd(ssOut + tid, (double)s);
        }
    }
}

// ---------------- qmaxpool over 19 entities per (agent, channel) -----------
__global__ void maxpool_k(const float* __restrict__ y2E,
                          const float* __restrict__ y2A,
                          float* __restrict__ pool)
{
    int idx = blockIdx.x * blockDim.x + threadIdx.x;
    if (idx >= NAg * 64) return;
    int agent = idx >> 6, c = idx & 63;
    float best = -1.f, b0 = 0.f, b1 = 0.f;
    #pragma unroll
    for (int e = 0; e < NE; e++) {
        size_t r = ((size_t)(agent * NE + e)) * 128 + c;
        float v0 = __ldg(y2E + r), v1 = __ldg(y2E + r + 64);
        float m = __fadd_rn(__fmul_rn(v0, v0), __fmul_rn(v1, v1));  // ref-exact mod
        if (m > best) { best = m; b0 = v0; b1 = v1; }
    }
    #pragma unroll
    for (int e = 0; e < NAL; e++) {
        size_t r = ((size_t)(agent * NAL + e)) * 128 + c;
        float v0 = __ldg(y2A + r), v1 = __ldg(y2A + r + 64);
        float m = __fadd_rn(__fmul_rn(v0, v0), __fmul_rn(v1, v1));
        if (m > best) { best = m; b0 = v0; b1 = v1; }
    }
    pool[(size_t)agent * 128 + c] = b0;
    pool[(size_t)agent * 128 + 64 + c] = b1;
}

// ---------------- imp third layer: 64->1 dot + scalar sumsq ----------------
__global__ void __launch_bounds__(256) imp3_k(
    const float* __restrict__ yE, const float* __restrict__ yA,
    const float* __restrict__ wE, const float* __restrict__ wA,
    float* __restrict__ y3, double* __restrict__ ssd)
{
    int gid = blockIdx.x * 256 + threadIdx.x;  // [0, 2*REc)
    bool isE = gid < REc;
    int row = isE ? gid : gid - REc;
    const float* src = (isE ? yE : yA) + (size_t)row * 64;
    const float* w = isE ? wE : wA;
    float s = 0.f;
    #pragma unroll
    for (int k4 = 0; k4 < 16; k4++) {
        float4 a = __ldg(reinterpret_cast<const float4*>(src) + k4);
        float4 b = __ldg(reinterpret_cast<const float4*>(w) + k4);
        s = fmaf(a.x, b.x, s); s = fmaf(a.y, b.y, s);
        s = fmaf(a.z, b.z, s); s = fmaf(a.w, b.w, s);
    }
    y3[gid] = s;
    __shared__ float red[256];
    red[threadIdx.x] = s * s;
    __syncthreads();
    for (int o = 128; o > 0; o >>= 1) {
        if (threadIdx.x < o) red[threadIdx.x] += red[threadIdx.x + o];
        __syncthreads();
    }
    if (threadIdx.x == 0) atomicAdd(ssd + (isE ? SS_IE3 : SS_IA3), (double)red[0]);
}

// ---------------- move_vec accumulation ----------------
__global__ void mv_k(const float* __restrict__ y3, const double* __restrict__ ssd,
                     float* __restrict__ mv)
{
    int idx = blockIdx.x * blockDim.x + threadIdx.x;  // [0, 2*PEc)
    if (idx >= 2 * PEc) return;
    bool isE = idx < PEc;
    int p = isE ? idx : idx - PEc;
    float m = (float)(ssd[isE ? SS_IE3 : SS_IA3] * (1.0 / REc));
    float denom = __fsqrt_rn(__fadd_rn(m, EPS_));
    size_t base = (isE ? (size_t)0 : (size_t)REc) + (size_t)p * 2;
    float b0 = __fdiv_rn(y3[base], denom);
    float b1 = __fdiv_rn(y3[base + 1], denom);
    float mod = __fsqrt_rn(__fadd_rn(__fmul_rn(b0, b0), __fmul_rn(b1, b1)));
    float coeff = __fdiv_rn(mod, fmaxf(1.f, mod));
    int agent = p / NE;
    atomicAdd(mv + agent * 2,     __fmul_rn(b0, coeff));
    atomicAdd(mv + agent * 2 + 1, __fmul_rn(b1, coeff));
}

// ---------------- final assembly: oaq head + move_q + attention dot --------
__device__ __forceinline__ float wred(float v) {
    #pragma unroll
    for (int o = 16; o; o >>= 1) v += __shfl_xor_sync(0xffffffffu, v, o);
    return v;
}

__global__ void __launch_bounds__(256) final_k(
    const float* __restrict__ oah, const float* __restrict__ Woa2,
    const float* __restrict__ boa2,
    const float* __restrict__ h2, const float* __restrict__ Wat3,
    const float* __restrict__ bat3,
    const float* __restrict__ mv, float* __restrict__ out)
{
    int agent = blockIdx.x * 8 + (threadIdx.x >> 5);
    int lane = threadIdx.x & 31;
    const float* oa = oah + (size_t)agent * 64;
    float o0 = oa[2 * lane], o1 = oa[2 * lane + 1];
    float q[3];
    #pragma unroll
    for (int j = 0; j < 3; j++) {
        float part = o0 * __ldg(Woa2 + (2 * lane) * 3 + j)
                   + o1 * __ldg(Woa2 + (2 * lane + 1) * 3 + j);
        q[j] = wred(part);
    }
    float w0 = __ldg(Wat3 + 2 * lane), w1 = __ldg(Wat3 + 2 * lane + 1);
    float aq[NE];
    #pragma unroll
    for (int e = 0; e < NE; e++) {
        const float* h = h2 + (size_t)(agent * NE + e) * 64;
        float part = h[2 * lane] * w0 + h[2 * lane + 1] * w1;
        aq[e] = wred(part);
    }
    if (lane == 0) {
        float* o = out + (size_t)agent * 16;
        float q2 = q[2] + boa2[2];
        float m0 = mv[agent * 2], m1 = mv[agent * 2 + 1];
        o[0] = q[0] + boa2[0];
        o[1] = q[1] + boa2[1];
        o[2] = q2 + m1;   // up
        o[3] = q2 - m1;   // down
        o[4] = q2 + m0;   // right
        o[5] = q2 - m0;   // left
        float b3 = bat3[0];
        #pragma unroll
        for (int e = 0; e < NE; e++) o[6 + e] = aq[e] + b3;
    }
}

// ---------------- launcher ----------------
extern "C" void kernel_launch(void* const* d_in, const int* in_sizes, int n_in,
                              void* d_out, int out_size)
{
    const float* own   = (const float*)d_in[0];
    const float* ef    = (const float*)d_in[1];
    const float* af    = (const float*)d_in[2];
    const float* W_e1  = (const float*)d_in[3];
    const float* W_e2  = (const float*)d_in[4];
    const float* W_a1  = (const float*)d_in[5];
    const float* W_a2  = (const float*)d_in[6];
    const float* W_f1  = (const float*)d_in[7];
    const float* W_f2  = (const float*)d_in[8];
    const float* W_ie1 = (const float*)d_in[9];
    const float* W_ie2 = (const float*)d_in[10];
    const float* W_ie3 = (const float*)d_in[11];
    const float* W_ia1 = (const float*)d_in[12];
    const float* W_ia2 = (const float*)d_in[13];
    const float* W_ia3 = (const float*)d_in[14];
    const float* W_oa1 = (const float*)d_in[15];
    const float* b_oa1 = (const float*)d_in[16];
    const float* W_oa2 = (const float*)d_in[17];
    const float* b_oa2 = (const float*)d_in[18];
    const float* W_at1 = (const float*)d_in[19];
    const float* b_at1 = (const float*)d_in[20];
    const float* W_at2 = (const float*)d_in[21];
    const float* b_at2 = (const float*)d_in[22];
    const float* W_at3 = (const float*)d_in[23];
    const float* b_at3 = (const float*)d_in[24];
    float* out = (float*)d_out;

    float* S = nullptr;
    cudaGetSymbolAddress((void**)&S, g_scratch);
    double* ssd = nullptr;
    cudaGetSymbolAddress((void**)&ssd, g_ssd);

    zero_k<<<80, 256>>>(S + OFF_MV, ssd);

    // layer 1 (ref-exact build_vec + W_e1/W_a1)
    layer1_k<<<(PEc + PAc) / 32, 64>>>(own, ef, af, W_e1, W_a1, S + OFF_Y1, ssd);
    act_k<<<(PEc * 64 + 255) / 256, 256>>>(S + OFF_Y1, ssd + SS_E1, PEc, 1.0 / REc, nullptr);
    act_k<<<(PAc * 64 + 255) / 256, 256>>>(S + OFF_Y1 + (size_t)REc * 64, ssd + SS_A1, PAc, 1.0 / RAc, nullptr);

    // layer 2
    gemm_k<64, 64, 0, false, true><<<REc / 64, 256>>>(S + OFF_Y1, S + OFF_Y2, W_e2, nullptr, ssd + SS_E2);
    gemm_k<64, 64, 0, false, true><<<RAc / 64, 256>>>(S + OFF_Y1 + (size_t)REc * 64,
                                                      S + OFF_Y2 + (size_t)REc * 64, W_a2, nullptr, ssd + SS_A2);
    act_k<<<(PEc * 64 + 255) / 256, 256>>>(S + OFF_Y2, ssd + SS_E2, PEc, 1.0 / REc, S + OFF_ESC);
    act_k<<<(PAc * 64 + 255) / 256, 256>>>(S + OFF_Y2 + (size_t)REc * 64, ssd + SS_A2, PAc, 1.0 / RAc, nullptr);

    // qmaxpool + f layers
    maxpool_k<<<(NAg * 64 + 255) / 256, 256>>>(S + OFF_Y2, S + OFF_Y2 + (size_t)REc * 64, S + OFF_POOL);
    gemm_k<64, 64, 0, false, true><<<(2 * NAg) / 64, 256>>>(S + OFF_POOL, S + OFF_YF1, W_f1, nullptr, ssd + SS_F1);
    act_k<<<(NAg * 64 + 255) / 256, 256>>>(S + OFF_YF1, ssd + SS_F1, NAg, 1.0 / (2 * NAg), nullptr);
    gemm_k<64, 64, 0, false, true><<<(2 * NAg) / 64, 256>>>(S + OFF_YF1, S + OFF_VF, W_f2, nullptr, ssd + SS_F2);
    act_k<<<(NAg * 64 + 255) / 256, 256>>>(S + OFF_VF, ssd + SS_F2, NAg, 1.0 / (2 * NAg), S + OFF_SF);

    // importance heads: split cat@W = vf@W_top + e_rc@W_bot
    gemm_k<64, 64, 0, false, false><<<(2 * NAg) / 64, 256>>>(S + OFF_VF, S + OFF_VCE, W_ie1, nullptr, nullptr);
    gemm_k<64, 64, 0, false, false><<<(2 * NAg) / 64, 256>>>(S + OFF_VF, S + OFF_VCA, W_ia1, nullptr, nullptr);
    gemm_k<64, 64, 2, false, true><<<REc / 64, 256>>>(S + OFF_Y2, S + OFF_YI1E, W_ie1 + 64 * 64, S + OFF_VCE, ssd + SS_IE1);
    gemm_k<64, 64, 2, false, true><<<REc / 64, 256>>>(S + OFF_Y2, S + OFF_YI1A, W_ia1 + 64 * 64, S + OFF_VCA, ssd + SS_IA1);
    act_k<<<(PEc * 64 + 255) / 256, 256>>>(S + OFF_YI1E, ssd + SS_IE1, PEc, 1.0 / REc, nullptr);
    act_k<<<(PEc * 64 + 255) / 256, 256>>>(S + OFF_YI1A, ssd + SS_IA1, PEc, 1.0 / REc, nullptr);
    gemm_k<64, 64, 0, false, true><<<REc / 64, 256>>>(S + OFF_YI1E, S + OFF_YI2E, W_ie2, nullptr, ssd + SS_IE2);
    gemm_k<64, 64, 0, false, true><<<REc / 64, 256>>>(S + OFF_YI1A, S + OFF_YI2A, W_ia2, nullptr, ssd + SS_IA2);
    act_k<<<(PEc * 64 + 255) / 256, 256>>>(S + OFF_YI2E, ssd + SS_IE2, PEc, 1.0 / REc, nullptr);
    act_k<<<(PEc * 64 + 255) / 256, 256>>>(S + OFF_YI2A, ssd + SS_IA2, PEc, 1.0 / REc, nullptr);
    imp3_k<<<(2 * REc) / 256, 256>>>(S + OFF_YI2E, S + OFF_YI2A, W_ie3, W_ia3, S + OFF_Y3, ssd);
    mv_k<<<(2 * PEc + 255) / 256, 256>>>(S + OFF_Y3, ssd, S + OFF_MV);

    // oaq hidden + attention head
    gemm_k<64, 64, 1, true, false><<<NAg / 64, 256>>>(S + OFF_SF, S + OFF_OAH, W_oa1, b_oa1, nullptr);
    gemm_k<64, 128, 1, false, false><<<NAg / 32, 256>>>(S + OFF_SF, S + OFF_SFC, W_at1, b_at1, nullptr);
    gemm_k<64, 128, 3, true, false><<<PEc / 32, 256>>>(S + OFF_ESC, S + OFF_H1, W_at1 + 64 * 128, S + OFF_SFC, nullptr);
    gemm_k<128, 64, 1, true, false><<<PEc / 64, 256>>>(S + OFF_H1, S + OFF_H2, W_at2, b_at2, nullptr);

    final_k<<<NAg / 8, 256>>>(S + OFF_OAH, W_oa2, b_oa2, S + OFF_H2, W_at3, b_at3, S + OFF_MV, out);

    (void)in_sizes; (void)n_in; (void)out_size;
}

// round 10
// speedup vs baseline: 1.4438x; 1.4438x over previous
#include <cuda_runtime.h>

// ---------------- problem constants ----------------
constexpr int NAg = 10240;           // B*NA agents
constexpr int NE  = 10, NAL = 9;
constexpr int PEc = NAg * NE;        // 102400 enemy pairs
constexpr int PAc = NAg * NAL;       // 92160 ally pairs
constexpr int REc = 2 * PEc;         // 204800 enemy rows
constexpr int RAc = 2 * PAc;         // 184320 ally rows
constexpr int RTc = REc + RAc;       // 389120
constexpr float EPS_ = 1e-5f;

// sumsq slots (within double ss block)
constexpr int SS_E1 = 0,   SS_A1 = 64,  SS_E2 = 128, SS_A2 = 192;
constexpr int SS_F1 = 256, SS_F2 = 320;
constexpr int SS_IE1 = 384, SS_IA1 = 448, SS_IE2 = 512, SS_IA2 = 576;
constexpr int SS_IE3 = 640, SS_IA3 = 641;

// ---------------- scratch layout (floats) ----------------
constexpr size_t OFF_Y1   = 0;
constexpr size_t OFF_Y2   = OFF_Y1   + (size_t)RTc * 64;
constexpr size_t OFF_ESC  = OFF_Y2   + (size_t)RTc * 64;
constexpr size_t OFF_POOL = OFF_ESC  + (size_t)PEc * 64;
constexpr size_t OFF_YF1  = OFF_POOL + (size_t)NAg * 128;
constexpr size_t OFF_VF   = OFF_YF1  + (size_t)NAg * 128;
constexpr size_t OFF_SF   = OFF_VF   + (size_t)NAg * 128;
constexpr size_t OFF_VCE  = OFF_SF   + (size_t)NAg * 64;
constexpr size_t OFF_VCA  = OFF_VCE  + (size_t)NAg * 128;
constexpr size_t OFF_SFC  = OFF_VCA  + (size_t)NAg * 128;
constexpr size_t OFF_YI1E = OFF_SFC  + (size_t)NAg * 128;
constexpr size_t OFF_YI1A = OFF_YI1E + (size_t)REc * 64;
constexpr size_t OFF_YI2E = OFF_YI1A + (size_t)REc * 64;
constexpr size_t OFF_YI2A = OFF_YI2E + (size_t)REc * 64;
constexpr size_t OFF_Y3   = OFF_YI2A + (size_t)REc * 64;
constexpr size_t OFF_H1   = OFF_Y3   + (size_t)2 * REc;
constexpr size_t OFF_AQ   = OFF_H1   + (size_t)PEc * 128;   // PEc floats
constexpr size_t OFF_OAH  = OFF_AQ   + (size_t)PEc;
constexpr size_t OFF_MV   = OFF_OAH  + (size_t)NAg * 64;
constexpr size_t SCR_TOTAL = OFF_MV + 20480;

__device__ __align__(16) float g_scratch[SCR_TOTAL];
__device__ __align__(16) double g_ssd[768];

// ---------------- zero kernel (mv floats + ss doubles) ----------------
__global__ void zero_k(float* __restrict__ mv, double* __restrict__ ssd) {
    int i = blockIdx.x * 256 + threadIdx.x;
    if (i < 20480) mv[i] = 0.f;
    if (i < 768) ssd[i] = 0.0;
}

// ---------------- ref-exact qbn+qrelu pair op ----------------
__device__ __forceinline__ void actpair(float& a, float& b, float denom) {
    a = __fdiv_rn(a, denom);
    b = __fdiv_rn(b, denom);
    float mod = __fsqrt_rn(__fadd_rn(__fmul_rn(a, a), __fmul_rn(b, b)));
    float coeff = fminf(mod, 1.f);          // == mod/max(1,mod) exactly
    a = __fmul_rn(a, coeff);
    b = __fmul_rn(b, coeff);
}

// ---------------- layer1: build_vec (ref-exact fp32) + 19-dot + sumsq ------
__global__ void __launch_bounds__(64) layer1_k(
    const float* __restrict__ own, const float* __restrict__ efeat,
    const float* __restrict__ afeat, const float* __restrict__ We,
    const float* __restrict__ Wa, float* __restrict__ y1,
    double* __restrict__ ssd)
{
    constexpr int PPB = 32;
    constexpr int EBLK = PEc / PPB;  // 3200
    const bool isE = blockIdx.x < EBLK;
    const int pbase = (isE ? blockIdx.x : blockIdx.x - EBLK) * PPB;
    const float* W = isE ? We : Wa;
    const float* feats = isE ? efeat : afeat;
    const int nper = isE ? NE : NAL;
    const int tid = threadIdx.x;

    __shared__ float ev0[PPB][20];
    __shared__ float ev1[PPB][20];

    if (tid < PPB) {
        int p = pbase + tid;
        const float* f = feats + (size_t)p * 9;
        const float* o = own + (size_t)(p / nper) * 11;
        float f2 = f[2], f3 = f[3];
        float pm = __fsqrt_rn(__fadd_rn(__fmul_rn(f2, f2), __fmul_rn(f3, f3)));
        bool mask = (pm == 0.f);
        float denom = mask ? 1.f : pm;
        ev0[tid][0] = f2; ev1[tid][0] = f3;
        float oth[7] = { f[0], f[1], f[4], f[5], f[6], f[7], f[8] };
        #pragma unroll
        for (int k = 0; k < 7; k++) {
            float om = __fsqrt_rn(__fmul_rn(2.f * oth[k], oth[k]));
            float u = mask ? 0.f : __fdiv_rn(om, denom);
            ev0[tid][1 + k] = __fmul_rn(f2, u);
            ev1[tid][1 + k] = __fmul_rn(f3, u);
        }
        #pragma unroll
        for (int k = 0; k < 11; k++) {
            float q = __fmul_rn(o[k], o[k]);
            float om = __fsqrt_rn(__fadd_rn(q, q));
            float u = mask ? 0.f : __fdiv_rn(om, denom);
            ev0[tid][8 + k] = __fmul_rn(f2, u);
            ev1[tid][8 + k] = __fmul_rn(f3, u);
        }
    }
    __syncthreads();

    float wr[19];
    #pragma unroll
    for (int k = 0; k < 19; k++) wr[k] = __ldg(W + k * 64 + tid);

    float ssa = 0.f;
    size_t rowG0 = (isE ? (size_t)0 : (size_t)REc) + (size_t)pbase * 2;
    for (int j = 0; j < PPB; j++) {
        float s0 = 0.f, s1 = 0.f;
        #pragma unroll
        for (int k = 0; k < 19; k++) {
            s0 = fmaf(ev0[j][k], wr[k], s0);
            s1 = fmaf(ev1[j][k], wr[k], s1);
        }
        y1[(rowG0 + 2 * j) * 64 + tid]     = s0;
        y1[(rowG0 + 2 * j + 1) * 64 + tid] = s1;
        ssa += s0 * s0 + s1 * s1;
    }
    atomicAdd(ssd + (isE ? SS_E1 : SS_A1) + tid, (double)ssa);
}

// ---------------- standalone act (for Y2, VF): in-place + optional merge ---
__global__ void act_k(float* __restrict__ y, const double* __restrict__ ssd,
                      int npairs, double invN, float* __restrict__ mergeOut)
{
    __shared__ float dsh[64];
    if (threadIdx.x < 64) {
        float m = (float)(ssd[threadIdx.x] * invN);
        dsh[threadIdx.x] = __fsqrt_rn(__fadd_rn(m, EPS_));
    }
    __syncthreads();
    int idx = blockIdx.x * 256 + threadIdx.x;
    if (idx >= npairs * 64) return;
    int p = idx >> 6, c = idx & 63;
    size_t i0 = (size_t)p * 128 + c;
    float a = y[i0], b = y[i0 + 64];
    actpair(a, b, dsh[c]);
    y[i0] = a; y[i0 + 64] = b;
    if (mergeOut)
        mergeOut[(size_t)p * 64 + c] = __fadd_rn(__fmul_rn(a, a), __fmul_rn(b, b));
}

// ---------------- generic dual-region GEMM ----------------
// out = act?(in) @ W (+add) (relu) ; optional column-sumsq ; optional 64->1 dot out
// ADDMODE: 0 none; 1 bias (N); 2 ar=((r>>1)/NE)*2+(r&1); 3 ar=r/NE  (r local)
template<int K, int N, int ADDMODE, bool RELU, bool WITH_SS, bool ACT_IN, bool DOT_OUT>
__global__ void __launch_bounds__(256) gemm_k(
    int splitBlk,
    const float* __restrict__ inA, const float* __restrict__ inB,
    float* __restrict__ outA, float* __restrict__ outB,
    const float* __restrict__ WA_, const float* __restrict__ WB_,
    const float* __restrict__ addA, const float* __restrict__ addB,
    double* __restrict__ ssOutA, double* __restrict__ ssOutB,
    const double* __restrict__ ssInA, const double* __restrict__ ssInB,
    double invNA, double invNB,
    const float* __restrict__ dotw, float* __restrict__ dotOut)
{
    const int reg = (blockIdx.x >= splitBlk) ? 1 : 0;
    const int blk = blockIdx.x - reg * splitBlk;
    const float* in  = reg ? inB  : inA;
    float* out       = reg ? outB : outA;
    const float* W   = reg ? WB_  : WA_;
    const float* addp= reg ? addB : addA;
    double* ssOut    = reg ? ssOutB : ssOutA;

    constexpr int CG = N / 4;
    constexpr int RG = 256 / CG;
    constexpr int TILE_R = RG * 4;
    __shared__ float xs[TILE_R][K + 4];
    __shared__ float red[(WITH_SS || DOT_OUT) ? RG * N : 1];
    __shared__ float scs[ACT_IN ? 64 : 1];

    const int tid = threadIdx.x;
    const int cg = tid % CG;
    const int rg = tid / CG;
    const int rowBase = blk * TILE_R;

    if (ACT_IN) {
        const double* ssIn = reg ? ssInB : ssInA;
        double invN = reg ? invNB : invNA;
        if (tid < 64) {
            float m = (float)(ssIn[tid] * invN);
            scs[tid] = __fsqrt_rn(__fadd_rn(m, EPS_));
        }
        __syncthreads();
    }

    if (ACT_IN) {
        // K == 64 in all ACT_IN uses; pair rows 2p, 2p+1 within tile
        #pragma unroll
        for (int i = tid; i < (TILE_R / 2) * 16; i += 256) {
            int pr = i >> 4, c = i & 15;
            const float* p0 = in + (size_t)(rowBase + 2 * pr) * 64 + c * 4;
            float4 v0 = __ldg((const float4*)p0);
            float4 v1 = __ldg((const float4*)(p0 + 64));
            actpair(v0.x, v1.x, scs[c * 4 + 0]);
            actpair(v0.y, v1.y, scs[c * 4 + 1]);
            actpair(v0.z, v1.z, scs[c * 4 + 2]);
            actpair(v0.w, v1.w, scs[c * 4 + 3]);
            *reinterpret_cast<float4*>(&xs[2 * pr][c * 4])     = v0;
            *reinterpret_cast<float4*>(&xs[2 * pr + 1][c * 4]) = v1;
        }
    } else {
        constexpr int KV = K / 4;
        #pragma unroll
        for (int i = tid; i < TILE_R * KV; i += 256) {
            int r = i / KV, c = i - r * KV;
            float4 v = __ldg(reinterpret_cast<const float4*>(in + (size_t)(rowBase + r) * K) + c);
            *reinterpret_cast<float4*>(&xs[r][c * 4]) = v;
        }
    }
    __syncthreads();

    float acc[4][4];
    #pragma unroll
    for (int i = 0; i < 4; i++)
        #pragma unroll
        for (int j = 0; j < 4; j++) acc[i][j] = 0.f;

    const float4* Wv = reinterpret_cast<const float4*>(W);
    const int r4 = rg * 4;
    #pragma unroll 2
    for (int k0 = 0; k0 < K; k0 += 4) {
        float xa[4][4];
        #pragma unroll
        for (int i = 0; i < 4; i++)
            *reinterpret_cast<float4*>(xa[i]) = *reinterpret_cast<const float4*>(&xs[r4 + i][k0]);
        #pragma unroll
        for (int kk = 0; kk < 4; kk++) {
            float4 b = __ldg(Wv + (k0 + kk) * CG + cg);
            #pragma unroll
            for (int i = 0; i < 4; i++) {
                float a = xa[i][kk];
                acc[i][0] = fmaf(a, b.x, acc[i][0]);
                acc[i][1] = fmaf(a, b.y, acc[i][1]);
                acc[i][2] = fmaf(a, b.z, acc[i][2]);
                acc[i][3] = fmaf(a, b.w, acc[i][3]);
            }
        }
    }

    float4 dw = make_float4(0.f, 0.f, 0.f, 0.f);
    if (DOT_OUT) dw = __ldg(reinterpret_cast<const float4*>(dotw) + cg);

    float ssl[4] = {0.f, 0.f, 0.f, 0.f};
    #pragma unroll
    for (int i = 0; i < 4; i++) {
        int r = rowBase + r4 + i;
        float4 a = make_float4(acc[i][0], acc[i][1], acc[i][2], acc[i][3]);
        if (ADDMODE == 1) {
            float4 bb = __ldg(reinterpret_cast<const float4*>(addp) + cg);
            a.x += bb.x; a.y += bb.y; a.z += bb.z; a.w += bb.w;
        } else if (ADDMODE == 2) {
            int ar = ((r >> 1) / NE) * 2 + (r & 1);
            float4 bb = __ldg(reinterpret_cast<const float4*>(addp + (size_t)ar * N) + cg);
            a.x += bb.x; a.y += bb.y; a.z += bb.z; a.w += bb.w;
        } else if (ADDMODE == 3) {
            int ar = r / NE;
            float4 bb = __ldg(reinterpret_cast<const float4*>(addp + (size_t)ar * N) + cg);
            a.x += bb.x; a.y += bb.y; a.z += bb.z; a.w += bb.w;
        }
        if (WITH_SS) {
            ssl[0] += a.x * a.x; ssl[1] += a.y * a.y;
            ssl[2] += a.z * a.z; ssl[3] += a.w * a.w;
        }
        if (RELU) {
            a.x = fmaxf(a.x, 0.f); a.y = fmaxf(a.y, 0.f);
            a.z = fmaxf(a.z, 0.f); a.w = fmaxf(a.w, 0.f);
        }
        if (DOT_OUT) {
            red[(r4 + i) * CG + cg] = a.x * dw.x + a.y * dw.y + a.z * dw.z + a.w * dw.w;
        } else {
            *(reinterpret_cast<float4*>(out + (size_t)r * N) + cg) = a;
        }
    }

    if (DOT_OUT) {
        __syncthreads();
        if (tid < TILE_R) {
            float s = 0.f;
            #pragma unroll
            for (int g = 0; g < CG; g++) s += red[tid * CG + g];
            dotOut[rowBase + tid] = s;
        }
    }
    if (WITH_SS) {
        *reinterpret_cast<float4*>(&red[rg * N + cg * 4]) =
            make_float4(ssl[0], ssl[1], ssl[2], ssl[3]);
        __syncthreads();
        if (tid < N) {
            float s = 0.f;
            #pragma unroll
            for (int g = 0; g < RG; g++) s += red[g * N + tid];
            atomicAdd(ssOut + tid, (double)s);
        }
    }
}

// ---------------- qmaxpool over 19 entities per (agent, channel) -----------
__global__ void maxpool_k(const float* __restrict__ y2E,
                          const float* __restrict__ y2A,
                          float* __restrict__ pool)
{
    int idx = blockIdx.x * blockDim.x + threadIdx.x;
    if (idx >= NAg * 64) return;
    int agent = idx >> 6, c = idx & 63;
    float best = -1.f, b0 = 0.f, b1 = 0.f;
    #pragma unroll
    for (int e = 0; e < NE; e++) {
        size_t r = ((size_t)(agent * NE + e)) * 128 + c;
        float v0 = __ldg(y2E + r), v1 = __ldg(y2E + r + 64);
        float m = __fadd_rn(__fmul_rn(v0, v0), __fmul_rn(v1, v1));
        if (m > best) { best = m; b0 = v0; b1 = v1; }
    }
    #pragma unroll
    for (int e = 0; e < NAL; e++) {
        size_t r = ((size_t)(agent * NAL + e)) * 128 + c;
        float v0 = __ldg(y2A + r), v1 = __ldg(y2A + r + 64);
        float m = __fadd_rn(__fmul_rn(v0, v0), __fmul_rn(v1, v1));
        if (m > best) { best = m; b0 = v0; b1 = v1; }
    }
    pool[(size_t)agent * 128 + c] = b0;
    pool[(size_t)agent * 128 + 64 + c] = b1;
}

// ---------------- imp3: fused act + 64->1 dot per pair + scalar sumsq ------
// BOTH regions have PEc pairs (e_imp and a_imp are computed from the same
// enemy-based `cat`). Grid = 2 * (PEc/256).
__global__ void __launch_bounds__(256) imp3f_k(
    const float* __restrict__ yi2,     // E rows then A rows, raw (pre-act)
    const float* __restrict__ wE, const float* __restrict__ wA,
    float* __restrict__ y3, double* __restrict__ ssd)
{
    constexpr int EBLK = PEc / 256;  // 400
    const int reg = (blockIdx.x >= EBLK) ? 1 : 0;
    const int pl = (blockIdx.x - reg * EBLK) * 256 + threadIdx.x;  // region-local pair

    __shared__ float rcs[64];
    if (threadIdx.x < 64) {
        float m = (float)(ssd[(reg ? SS_IA2 : SS_IE2) + threadIdx.x] * (1.0 / REc));
        rcs[threadIdx.x] = __fsqrt_rn(__fadd_rn(m, EPS_));
    }
    __syncthreads();

    int gp = reg ? (PEc + pl) : pl;
    const float* src = yi2 + (size_t)(2 * gp) * 64;
    const float* w = reg ? wA : wE;

    float s0 = 0.f, s1 = 0.f;
    #pragma unroll
    for (int k4 = 0; k4 < 16; k4++) {
        float4 v0 = __ldg(reinterpret_cast<const float4*>(src) + k4);
        float4 v1 = __ldg(reinterpret_cast<const float4*>(src + 64) + k4);
        float4 dn = *reinterpret_cast<const float4*>(&rcs[k4 * 4]);
        float4 wv = __ldg(reinterpret_cast<const float4*>(w) + k4);
        #pragma unroll
        for (int j = 0; j < 4; j++) {
            float a = ((const float*)&v0)[j];
            float b = ((const float*)&v1)[j];
            actpair(a, b, ((const float*)&dn)[j]);
            float ww = ((const float*)&wv)[j];
            s0 = fmaf(a, ww, s0);
            s1 = fmaf(b, ww, s1);
        }
    }
    y3[2 * gp] = s0;
    y3[2 * gp + 1] = s1;

    __shared__ float red[256];
    red[threadIdx.x] = s0 * s0 + s1 * s1;
    __syncthreads();
    for (int o = 128; o > 0; o >>= 1) {
        if (threadIdx.x < o) red[threadIdx.x] += red[threadIdx.x + o];
        __syncthreads();
    }
    if (threadIdx.x == 0) atomicAdd(ssd + (reg ? SS_IA3 : SS_IE3), (double)red[0]);
}

// ---------------- move_vec accumulation ----------------
__global__ void mv_k(const float* __restrict__ y3, const double* __restrict__ ssd,
                     float* __restrict__ mv)
{
    int idx = blockIdx.x * blockDim.x + threadIdx.x;
    if (idx >= 2 * PEc) return;
    bool isE = idx < PEc;
    int p = isE ? idx : idx - PEc;
    float m = (float)(ssd[isE ? SS_IE3 : SS_IA3] * (1.0 / REc));
    float denom = __fsqrt_rn(__fadd_rn(m, EPS_));
    size_t base = (isE ? (size_t)0 : (size_t)REc) + (size_t)p * 2;
    float b0 = __fdiv_rn(y3[base], denom);
    float b1 = __fdiv_rn(y3[base + 1], denom);
    float mod = __fsqrt_rn(__fadd_rn(__fmul_rn(b0, b0), __fmul_rn(b1, b1)));
    float coeff = fminf(mod, 1.f);
    int agent = p / NE;
    atomicAdd(mv + agent * 2,     __fmul_rn(b0, coeff));
    atomicAdd(mv + agent * 2 + 1, __fmul_rn(b1, coeff));
}

// ---------------- final assembly ----------------
__device__ __forceinline__ float wred(float v) {
    #pragma unroll
    for (int o = 16; o; o >>= 1) v += __shfl_xor_sync(0xffffffffu, v, o);
    return v;
}

__global__ void __launch_bounds__(256) final_k(
    const float* __restrict__ oah, const float* __restrict__ Woa2,
    const float* __restrict__ boa2,
    const float* __restrict__ aqbuf, const float* __restrict__ bat3,
    const float* __restrict__ mv, float* __restrict__ out)
{
    int agent = blockIdx.x * 8 + (threadIdx.x >> 5);
    int lane = threadIdx.x & 31;
    const float* oa = oah + (size_t)agent * 64;
    float o0 = oa[2 * lane], o1 = oa[2 * lane + 1];
    float q[3];
    #pragma unroll
    for (int j = 0; j < 3; j++) {
        float part = o0 * __ldg(Woa2 + (2 * lane) * 3 + j)
                   + o1 * __ldg(Woa2 + (2 * lane + 1) * 3 + j);
        q[j] = wred(part);
    }
    float* o = out + (size_t)agent * 16;
    if (lane == 0) {
        float q2 = q[2] + boa2[2];
        float m0 = mv[agent * 2], m1 = mv[agent * 2 + 1];
        o[0] = q[0] + boa2[0];
        o[1] = q[1] + boa2[1];
        o[2] = q2 + m1;
        o[3] = q2 - m1;
        o[4] = q2 + m0;
        o[5] = q2 - m0;
    }
    if (lane < NE)
        o[6 + lane] = aqbuf[(size_t)agent * NE + lane] + bat3[0];
}

// ---------------- launcher ----------------
extern "C" void kernel_launch(void* const* d_in, const int* in_sizes, int n_in,
                              void* d_out, int out_size)
{
    const float* own   = (const float*)d_in[0];
    const float* ef    = (const float*)d_in[1];
    const float* af    = (const float*)d_in[2];
    const float* W_e1  = (const float*)d_in[3];
    const float* W_e2  = (const float*)d_in[4];
    const float* W_a1  = (const float*)d_in[5];
    const float* W_a2  = (const float*)d_in[6];
    const float* W_f1  = (const float*)d_in[7];
    const float* W_f2  = (const float*)d_in[8];
    const float* W_ie1 = (const float*)d_in[9];
    const float* W_ie2 = (const float*)d_in[10];
    const float* W_ie3 = (const float*)d_in[11];
    const float* W_ia1 = (const float*)d_in[12];
    const float* W_ia2 = (const float*)d_in[13];
    const float* W_ia3 = (const float*)d_in[14];
    const float* W_oa1 = (const float*)d_in[15];
    const float* b_oa1 = (const float*)d_in[16];
    const float* W_oa2 = (const float*)d_in[17];
    const float* b_oa2 = (const float*)d_in[18];
    const float* W_at1 = (const float*)d_in[19];
    const float* b_at1 = (const float*)d_in[20];
    const float* W_at2 = (const float*)d_in[21];
    const float* b_at2 = (const float*)d_in[22];
    const float* W_at3 = (const float*)d_in[23];
    const float* b_at3 = (const float*)d_in[24];
    float* out = (float*)d_out;

    float* S = nullptr;
    cudaGetSymbolAddress((void**)&S, g_scratch);
    double* ssd = nullptr;
    cudaGetSymbolAddress((void**)&ssd, g_ssd);

    zero_k<<<80, 256>>>(S + OFF_MV, ssd);

    // layer 1 (ref-exact build_vec + W_e1/W_a1), raw output + ss E1/A1
    layer1_k<<<(PEc + PAc) / 32, 64>>>(own, ef, af, W_e1, W_a1, S + OFF_Y1, ssd);

    // layer 2, dual region, act(Y1) fused on load, ss E2/A2
    gemm_k<64, 64, 0, false, true, true, false><<<RTc / 64, 256>>>(
        REc / 64,
        S + OFF_Y1, S + OFF_Y1 + (size_t)REc * 64,
        S + OFF_Y2, S + OFF_Y2 + (size_t)REc * 64,
        W_e2, W_a2, nullptr, nullptr,
        ssd + SS_E2, ssd + SS_A2,
        ssd + SS_E1, ssd + SS_A1, 1.0 / REc, 1.0 / RAc,
        nullptr, nullptr);

    // act(Y2) materialized (pool path; E with merge -> ESC)
    act_k<<<(PEc * 64) / 256, 256>>>(S + OFF_Y2, ssd + SS_E2, PEc, 1.0 / REc, S + OFF_ESC);
    act_k<<<(PAc * 64) / 256, 256>>>(S + OFF_Y2 + (size_t)REc * 64, ssd + SS_A2, PAc, 1.0 / RAc, nullptr);

    // pool + f layers
    maxpool_k<<<(NAg * 64) / 256, 256>>>(S + OFF_Y2, S + OFF_Y2 + (size_t)REc * 64, S + OFF_POOL);
    gemm_k<64, 64, 0, false, true, false, false><<<(2 * NAg) / 64, 256>>>(
        (2 * NAg) / 64, S + OFF_POOL, S + OFF_POOL, S + OFF_YF1, S + OFF_YF1,
        W_f1, W_f1, nullptr, nullptr, ssd + SS_F1, ssd + SS_F1,
        nullptr, nullptr, 0.0, 0.0, nullptr, nullptr);
    gemm_k<64, 64, 0, false, true, true, false><<<(2 * NAg) / 64, 256>>>(
        (2 * NAg) / 64, S + OFF_YF1, S + OFF_YF1, S + OFF_VF, S + OFF_VF,
        W_f2, W_f2, nullptr, nullptr, ssd + SS_F2, ssd + SS_F2,
        ssd + SS_F1, ssd + SS_F1, 1.0 / (2 * NAg), 1.0 / (2 * NAg), nullptr, nullptr);
    act_k<<<(NAg * 64) / 256, 256>>>(S + OFF_VF, ssd + SS_F2, NAg, 1.0 / (2 * NAg), S + OFF_SF);

    // vf @ top-half of W_ie1 / W_ia1 (dual)
    gemm_k<64, 64, 0, false, false, false, false><<<2 * ((2 * NAg) / 64), 256>>>(
        (2 * NAg) / 64, S + OFF_VF, S + OFF_VF, S + OFF_VCE, S + OFF_VCA,
        W_ie1, W_ia1, nullptr, nullptr, nullptr, nullptr,
        nullptr, nullptr, 0.0, 0.0, nullptr, nullptr);

    // importance layer 1 (dual: both read Y2 E region), ss IE1/IA1
    gemm_k<64, 64, 2, false, true, false, false><<<2 * (REc / 64), 256>>>(
        REc / 64, S + OFF_Y2, S + OFF_Y2, S + OFF_YI1E, S + OFF_YI1A,
        W_ie1 + 64 * 64, W_ia1 + 64 * 64, S + OFF_VCE, S + OFF_VCA,
        ssd + SS_IE1, ssd + SS_IA1, nullptr, nullptr, 0.0, 0.0, nullptr, nullptr);

    // importance layer 2 (dual, act fused on load), ss IE2/IA2
    gemm_k<64, 64, 0, false, true, true, false><<<2 * (REc / 64), 256>>>(
        REc / 64, S + OFF_YI1E, S + OFF_YI1A, S + OFF_YI2E, S + OFF_YI2A,
        W_ie2, W_ia2, nullptr, nullptr,
        ssd + SS_IE2, ssd + SS_IA2,
        ssd + SS_IE1, ssd + SS_IA1, 1.0 / REc, 1.0 / REc, nullptr, nullptr);

    // importance layer 3 (act fused) + move vec — BOTH regions PEc pairs
    imp3f_k<<<2 * (PEc / 256), 256>>>(S + OFF_YI2E, W_ie3, W_ia3, S + OFF_Y3, ssd);
    mv_k<<<(2 * PEc + 255) / 256, 256>>>(S + OFF_Y3, ssd, S + OFF_MV);

    // oaq hidden
    gemm_k<64, 64, 1, true, false, false, false><<<NAg / 64, 256>>>(
        NAg / 64, S + OFF_SF, S + OFF_SF, S + OFF_OAH, S + OFF_OAH,
        W_oa1, W_oa1, b_oa1, b_oa1, nullptr, nullptr,
        nullptr, nullptr, 0.0, 0.0, nullptr, nullptr);

    // attention head: sf@W_at1_top + bias (per agent), then pair rows
    gemm_k<64, 128, 1, false, false, false, false><<<NAg / 32, 256>>>(
        NAg / 32, S + OFF_SF, S + OFF_SF, S + OFF_SFC, S + OFF_SFC,
        W_at1, W_at1, b_at1, b_at1, nullptr, nullptr,
        nullptr, nullptr, 0.0, 0.0, nullptr, nullptr);
    gemm_k<64, 128, 3, true, false, false, false><<<PEc / 32, 256>>>(
        PEc / 32, S + OFF_ESC, S + OFF_ESC, S + OFF_H1, S + OFF_H1,
        W_at1 + 64 * 128, W_at1 + 64 * 128, S + OFF_SFC, S + OFF_SFC,
        nullptr, nullptr, nullptr, nullptr, 0.0, 0.0, nullptr, nullptr);
    // H2 with fused W_at3 dot -> aq
    gemm_k<128, 64, 1, true, false, false, true><<<PEc / 64, 256>>>(
        PEc / 64, S + OFF_H1, S + OFF_H1, nullptr, nullptr,
        W_at2, W_at2, b_at2, b_at2, nullptr, nullptr,
        nullptr, nullptr, 0.0, 0.0, W_at3, S + OFF_AQ);

    final_k<<<NAg / 8, 256>>>(S + OFF_OAH, W_oa2, b_oa2, S + OFF_AQ, b_at3, S + OFF_MV, out);

    (void)in_sizes; (void)n_in; (void)out_size;
}